// round 13
// baseline (speedup 1.0000x reference)
#include <cuda_runtime.h>
#include <cuda_fp16.h>
#include <math.h>
#include <stdint.h>

#define NMAX 100000
#define EMAX 1000000
#define GMAXG 512

// ---------------- scratch (device globals; no allocation allowed) ----------------
__device__ float   g_h[NMAX * 64];        // residual stream
__device__ float   g_t[NMAX * 64];        // post-attention / pre-BN buffer
__device__ __half2 g_qh[NMAX * 32];       // q fp16
__device__ __half2 g_kh[NMAX * 32];       // k fp16
__device__ __half2 g_vh[NMAX * 32];       // v fp16
__device__ __half2 g_ph[NMAX * 32];       // p_h = We_h @ q_h fp16
__device__ float   g_r[NMAX * 4];         // r_h = q_h . be_h
__device__ float   g_skip[NMAX * 64];
__device__ float   g_bnsum3[192];         // per-layer BN sums (3 x 64)
__device__ float   g_bnsq3[192];
__device__ float   g_pool[GMAXG * 64];
__device__ float   g_cnt[GMAXG];
// CSR / sorted edge stream (built once per launch; edge list is layer-invariant)
__device__ int     g_cnt_n[NMAX];
__device__ int     g_row[NMAX + 1];
__device__ int     g_wp[NMAX];
__device__ int     g_bsum[128];
__device__ int     g_ssrc[EMAX];
__device__ __half2 g_seah[EMAX * 8];
// degree-sorted node permutation (load balance for edge_agg)
__device__ int     g_perm[NMAX];
__device__ int     g_dhist[256];
__device__ int     g_dwp[256];

static inline unsigned divup(long long a, int b) { return (unsigned)((a + b - 1) / b); }

__device__ __forceinline__ void redAddV4(float* addr, float a, float b, float c, float d) {
    asm volatile("red.global.add.v4.f32 [%0], {%1,%2,%3,%4};"
                 :: "l"(addr), "f"(a), "f"(b), "f"(c), "f"(d) : "memory");
}
__device__ __forceinline__ float2 h2f(unsigned u) {
    return __half22float2(*reinterpret_cast<const __half2*>(&u));
}
__device__ __forceinline__ unsigned f2tf32(float x) {
    unsigned r;
    asm("cvt.rna.tf32.f32 %0, %1;" : "=r"(r) : "f"(x));
    return r;
}
__device__ __forceinline__ void mma_tf32(float* d, const unsigned* a, unsigned b0, unsigned b1) {
    asm volatile(
        "mma.sync.aligned.m16n8k8.row.col.f32.tf32.tf32.f32 "
        "{%0,%1,%2,%3}, {%4,%5,%6,%7}, {%8,%9}, {%0,%1,%2,%3};"
        : "+f"(d[0]), "+f"(d[1]), "+f"(d[2]), "+f"(d[3])
        : "r"(a[0]), "r"(a[1]), "r"(a[2]), "r"(a[3]), "r"(b0), "r"(b1));
}

// ---------------- initial node linear: out[n,64] = in[n,32] @ W[32,64] + b ----------------
__global__ void lin32_kernel(const float* __restrict__ in, const float* __restrict__ W,
                             const float* __restrict__ bias, float* __restrict__ out, int n) {
    __shared__ float sW[32 * 64];
    __shared__ float sb[64];
    for (int i = threadIdx.x; i < 32 * 64; i += blockDim.x) sW[i] = W[i];
    if (threadIdx.x < 64) sb[threadIdx.x] = bias[threadIdx.x];
    __syncthreads();
    int node = blockIdx.x * blockDim.x + threadIdx.x;
    if (node >= n) return;
    float4 acc[16];
#pragma unroll
    for (int j = 0; j < 16; j++) {
        acc[j].x = sb[4 * j + 0]; acc[j].y = sb[4 * j + 1];
        acc[j].z = sb[4 * j + 2]; acc[j].w = sb[4 * j + 3];
    }
    const float4* inp = reinterpret_cast<const float4*>(in + (size_t)node * 32);
#pragma unroll
    for (int c = 0; c < 8; c++) {
        float4 x4 = inp[c];
        float xs[4] = {x4.x, x4.y, x4.z, x4.w};
#pragma unroll
        for (int kk = 0; kk < 4; kk++) {
            float x = xs[kk];
            const float4* wr = reinterpret_cast<const float4*>(&sW[(c * 4 + kk) * 64]);
#pragma unroll
            for (int j = 0; j < 16; j++) {
                float4 w = wr[j];
                acc[j].x += x * w.x; acc[j].y += x * w.y;
                acc[j].z += x * w.z; acc[j].w += x * w.w;
            }
        }
    }
    float4* op = reinterpret_cast<float4*>(out + (size_t)node * 64);
#pragma unroll
    for (int j = 0; j < 16; j++) op[j] = acc[j];
}

// ---------------- CSR build (once per launch) ----------------
__global__ void hist_clear_kernel(int n) {
    int i = blockIdx.x * blockDim.x + threadIdx.x;
    if (i < n) g_cnt_n[i] = 0;
    if (i < 256) g_dhist[i] = 0;
    if (i < 192) { g_bnsum3[i] = 0.0f; g_bnsq3[i] = 0.0f; }
}
__global__ void hist_kernel(const int* __restrict__ ei, int e) {
    int i = blockIdx.x * blockDim.x + threadIdx.x;
    if (i < e) atomicAdd(&g_cnt_n[ei[e + i]], 1);
}
__global__ void scan1_kernel(int n) {
    __shared__ int sm[1024];
    int i = blockIdx.x * 1024 + threadIdx.x;
    int v = (i < n) ? g_cnt_n[i] : 0;
    sm[threadIdx.x] = v;
    __syncthreads();
    for (int off = 1; off < 1024; off <<= 1) {
        int t = (threadIdx.x >= off) ? sm[threadIdx.x - off] : 0;
        __syncthreads();
        sm[threadIdx.x] += t;
        __syncthreads();
    }
    if (i < n) g_row[i + 1] = sm[threadIdx.x];
    if (threadIdx.x == 1023) g_bsum[blockIdx.x] = sm[1023];
}
__global__ void scan2_kernel(int nb) {
    if (threadIdx.x == 0) {
        int acc = 0;
        for (int b = 0; b < nb; b++) { int t = g_bsum[b]; g_bsum[b] = acc; acc += t; }
    }
}
__global__ void scan3_kernel(int n) {
    int i = blockIdx.x * 1024 + threadIdx.x;
    if (i < n) {
        int incl = g_row[i + 1] + g_bsum[blockIdx.x];
        g_row[i + 1] = incl;
        g_wp[i] = incl - g_cnt_n[i];
    }
    if (i == 0) g_row[0] = 0;
}
__global__ void scatter_kernel(const int* __restrict__ ei, const float* __restrict__ eattr, int e) {
    int eid = blockIdx.x * 256 + threadIdx.x;
    if (eid >= e) return;
    int dst = ei[e + eid];
    int pos = atomicAdd(&g_wp[dst], 1);
    g_ssrc[pos] = ei[eid];
    const float4* ea = reinterpret_cast<const float4*>(eattr + (size_t)eid * 16);
    __half2 hp[8];
#pragma unroll
    for (int jj = 0; jj < 4; jj++) {
        float4 v = ea[jj];
        hp[2 * jj]     = __floats2half2_rn(v.x, v.y);
        hp[2 * jj + 1] = __floats2half2_rn(v.z, v.w);
    }
    uint4* dp = reinterpret_cast<uint4*>(g_seah + (size_t)pos * 8);
    dp[0] = *reinterpret_cast<uint4*>(&hp[0]);
    dp[1] = *reinterpret_cast<uint4*>(&hp[4]);
}

// ---------------- degree-sorted permutation (load balance) ----------------
__global__ void deg_hist_kernel(int n) {
    int i = blockIdx.x * blockDim.x + threadIdx.x;
    if (i >= n) return;
    int d = g_row[i + 1] - g_row[i];
    if (d > 255) d = 255;
    atomicAdd(&g_dhist[d], 1);
}
__global__ void deg_scan_kernel() {
    __shared__ int sm[256];
    int t = threadIdx.x;
    sm[t] = g_dhist[t];
    __syncthreads();
    for (int off = 1; off < 256; off <<= 1) {
        int v = (t >= off) ? sm[t - off] : 0;
        __syncthreads();
        sm[t] += v;
        __syncthreads();
    }
    g_dwp[t] = sm[t] - g_dhist[t];   // exclusive
}
__global__ void deg_scatter_kernel(int n) {
    int i = blockIdx.x * blockDim.x + threadIdx.x;
    if (i >= n) return;
    int d = g_row[i + 1] - g_row[i];
    if (d > 255) d = 255;
    int pos = atomicAdd(&g_dwp[d], 1);
    g_perm[pos] = i;
}

// ---------------- fused q/k/v/skip (tf32 mma) + p/r + optional BN/GELU/residual on input ----------------
// block = 256 threads (8 warps) = 64 nodes.
#define XS_STRIDE 68
#define SW_STRIDE 72
__global__ void qkvs_kernel(const float* __restrict__ Wq, const float* __restrict__ bq,
                            const float* __restrict__ Wk, const float* __restrict__ bk,
                            const float* __restrict__ Wv, const float* __restrict__ bv,
                            const float* __restrict__ Ws, const float* __restrict__ bs,
                            const float* __restrict__ We, const float* __restrict__ be,
                            const float* __restrict__ gamma, const float* __restrict__ beta,
                            const float* __restrict__ bnsum, const float* __restrict__ bnsq,
                            int apply_bn, int n) {
    __shared__ float xs[64 * XS_STRIDE];
    __shared__ float sW[64 * SW_STRIDE];
    __shared__ float sb[64];
    __shared__ float sWe[16 * 64];
    __shared__ float sbe[64];
    __shared__ __half qbuf[64 * 64];
    const int tid = threadIdx.x;
    const int base = blockIdx.x * 64;
    const float invN = 1.0f / (float)n;

    // input tile: either plain g_h, or h_new = gelu(bn(g_t)) + g_h (fused bn_apply),
    // in which case g_h is updated too.
    for (int idx = tid; idx < 64 * 16; idx += 256) {
        int nl = idx >> 4, kk = idx & 15;
        int gn = base + nl;
        if (gn < n) {
            float4 h4 = reinterpret_cast<const float4*>(g_h)[gn * 16 + kk];
            if (apply_bn) {
                float4 t4 = reinterpret_cast<const float4*>(g_t)[gn * 16 + kk];
                float tt[4] = {t4.x, t4.y, t4.z, t4.w};
                float hh[4] = {h4.x, h4.y, h4.z, h4.w};
                float r[4];
#pragma unroll
                for (int k = 0; k < 4; k++) {
                    int c = kk * 4 + k;
                    float mu = bnsum[c] * invN;
                    float var = bnsq[c] * invN - mu * mu;
                    float y = gamma[c] * (tt[k] - mu) * rsqrtf(var + 1e-5f) + beta[c];
                    float gl = 0.5f * y * (1.0f + erff(y * 0.70710678118654752f));
                    r[k] = gl + hh[k];
                }
                h4.x = r[0]; h4.y = r[1]; h4.z = r[2]; h4.w = r[3];
                reinterpret_cast<float4*>(g_h)[gn * 16 + kk] = h4;
            }
            float* p = &xs[nl * XS_STRIDE + kk * 4];
            p[0] = h4.x; p[1] = h4.y; p[2] = h4.z; p[3] = h4.w;
        }
    }
    for (int i = tid; i < 1024; i += 256) sWe[i] = We[i];
    if (tid < 64) sbe[tid] = be[tid];

    const float* Wm[4] = {Wq, Wk, Wv, Ws};
    const float* bm[4] = {bq, bk, bv, bs};

    const int warp = tid >> 5, lane = tid & 31;
    const int g4 = warp >> 1;
    const int chalf = warp & 1;
    const int grp = lane >> 2;
    const int qd = lane & 3;
    const int nl = tid & 63;
    const int quart = tid >> 6;
    const int gn = base + nl;

    for (int m = 0; m < 4; m++) {
        __syncthreads();
        {
            const float* wsrc = Wm[m];
            for (int i = tid; i < 4096; i += 256) {
                sW[(i >> 6) * SW_STRIDE + (i & 63)] = __uint_as_float(f2tf32(wsrc[i]));
            }
            if (tid < 64) sb[tid] = bm[m][tid];
        }
        __syncthreads();

        float acc[4][4];
#pragma unroll
        for (int t = 0; t < 4; t++)
#pragma unroll
            for (int d = 0; d < 4; d++) acc[t][d] = 0.0f;

#pragma unroll
        for (int ks = 0; ks < 8; ks++) {
            unsigned a[4];
            const float* xr = &xs[(g4 * 16 + grp) * XS_STRIDE + ks * 8 + qd];
            a[0] = f2tf32(xr[0]);
            a[2] = f2tf32(xr[4]);
            a[1] = f2tf32(xr[8 * XS_STRIDE]);
            a[3] = f2tf32(xr[8 * XS_STRIDE + 4]);
#pragma unroll
            for (int t = 0; t < 4; t++) {
                int cb = chalf * 32 + t * 8;
                unsigned b0 = __float_as_uint(sW[(ks * 8 + qd) * SW_STRIDE + cb + grp]);
                unsigned b1 = __float_as_uint(sW[(ks * 8 + qd + 4) * SW_STRIDE + cb + grp]);
                mma_tf32(acc[t], a, b0, b1);
            }
        }

        int r0 = g4 * 16 + grp;
        if (m == 3) {
#pragma unroll
            for (int t = 0; t < 4; t++) {
                int col = chalf * 32 + t * 8 + qd * 2;
                if (base + r0 < n) {
                    float2 o; o.x = acc[t][0] + sb[col]; o.y = acc[t][1] + sb[col + 1];
                    *reinterpret_cast<float2*>(g_skip + (size_t)(base + r0) * 64 + col) = o;
                }
                if (base + r0 + 8 < n) {
                    float2 o; o.x = acc[t][2] + sb[col]; o.y = acc[t][3] + sb[col + 1];
                    *reinterpret_cast<float2*>(g_skip + (size_t)(base + r0 + 8) * 64 + col) = o;
                }
            }
        } else {
#pragma unroll
            for (int t = 0; t < 4; t++) {
                int col = chalf * 32 + t * 8 + qd * 2;
                __half2 hlo = __floats2half2_rn(acc[t][0] + sb[col], acc[t][1] + sb[col + 1]);
                __half2 hhi = __floats2half2_rn(acc[t][2] + sb[col], acc[t][3] + sb[col + 1]);
                if (m == 0) {
                    *reinterpret_cast<__half2*>(&qbuf[r0 * 64 + col]) = hlo;
                    *reinterpret_cast<__half2*>(&qbuf[(r0 + 8) * 64 + col]) = hhi;
                } else {
                    __half2* dst = (m == 1) ? g_kh : g_vh;
                    if (base + r0 < n)     dst[(size_t)(base + r0) * 32 + (col >> 1)] = hlo;
                    if (base + r0 + 8 < n) dst[(size_t)(base + r0 + 8) * 32 + (col >> 1)] = hhi;
                }
            }
            if (m == 0) {
                __syncthreads();
                if (gn < n) {
                    uint4 u0 = *reinterpret_cast<const uint4*>(&qbuf[nl * 64 + quart * 16]);
                    uint4 u1 = *reinterpret_cast<const uint4*>(&qbuf[nl * 64 + quart * 16 + 8]);
                    uint4* qp = reinterpret_cast<uint4*>(g_qh + (size_t)gn * 32 + quart * 8);
                    qp[0] = u0; qp[1] = u1;
                    float qv[16];
                    {
                        const unsigned* uw = reinterpret_cast<const unsigned*>(&u0);
#pragma unroll
                        for (int j = 0; j < 4; j++) {
                            float2 f = h2f(uw[j]); qv[2 * j] = f.x; qv[2 * j + 1] = f.y;
                        }
                        const unsigned* uw1 = reinterpret_cast<const unsigned*>(&u1);
#pragma unroll
                        for (int j = 0; j < 4; j++) {
                            float2 f = h2f(uw1[j]); qv[8 + 2 * j] = f.x; qv[9 + 2 * j] = f.y;
                        }
                    }
                    float pc[16];
#pragma unroll
                    for (int c = 0; c < 16; c++) {
                        const float4* wr = reinterpret_cast<const float4*>(&sWe[c * 64 + quart * 16]);
                        float s = 0.0f;
#pragma unroll
                        for (int j = 0; j < 4; j++) {
                            float4 w = wr[j];
                            s += w.x * qv[4 * j] + w.y * qv[4 * j + 1]
                               + w.z * qv[4 * j + 2] + w.w * qv[4 * j + 3];
                        }
                        pc[c] = s;
                    }
                    float rr = 0.0f;
#pragma unroll
                    for (int d = 0; d < 16; d++) rr += sbe[quart * 16 + d] * qv[d];
                    __half2 hp[8];
#pragma unroll
                    for (int j = 0; j < 8; j++) hp[j] = __floats2half2_rn(pc[2 * j], pc[2 * j + 1]);
                    uint4* pp = reinterpret_cast<uint4*>(g_ph + (size_t)gn * 32 + quart * 8);
                    pp[0] = *reinterpret_cast<uint4*>(&hp[0]);
                    pp[1] = *reinterpret_cast<uint4*>(&hp[4]);
                    g_r[gn * 4 + quart] = rr;
                }
            }
        }
    }
}

// ---------------- edge aggregation + finalize, fused; zero atomics; degree-sorted nodes ----------------
__global__ void edge_agg_kernel(const float* __restrict__ We, const float* __restrict__ be, int n) {
    __shared__ float sWe[16 * 64];
    __shared__ float sbe[64];
    const int tid = threadIdx.x;
    for (int i = tid; i < 1024; i += 256) sWe[i] = We[i];
    if (tid < 64) sbe[tid] = be[tid];
    __syncthreads();

    int idx = blockIdx.x * 256 + tid;   // (node slot, j)
    if (idx >= n * 4) return;
    const int node = g_perm[idx >> 2];
    const int j = idx & 3;
    const unsigned lane = tid & 31;
    const unsigned gmask = 0xFu << (lane & 28);
    const int lbase = lane & 28;

    const uint2* qb = reinterpret_cast<const uint2*>(g_qh + (size_t)node * 32 + j * 2);
    const uint2* pb = reinterpret_cast<const uint2*>(g_ph + (size_t)node * 32 + j * 2);
    uint2 qv[4], pv[4];
#pragma unroll
    for (int i = 0; i < 4; i++) { qv[i] = qb[i * 4]; pv[i] = pb[i * 4]; }
    const float rj = g_r[node * 4 + j];

    const int rs = g_row[node], re = g_row[node + 1];
    float at[4][4], as_[4][4], ad[4];
#pragma unroll
    for (int i = 0; i < 4; i++) {
        ad[i] = 0.0f;
#pragma unroll
        for (int d = 0; d < 4; d++) { at[i][d] = 0.0f; as_[i][d] = 0.0f; }
    }

    for (int pos = rs; pos < re; pos++) {
        int src = g_ssrc[pos];
        uint2 eaw = *reinterpret_cast<const uint2*>(g_seah + (size_t)pos * 8 + j * 2);
        float2 ea0 = h2f(eaw.x), ea1 = h2f(eaw.y);
        const uint2* kb = reinterpret_cast<const uint2*>(g_kh + (size_t)src * 32 + j * 2);
        const uint2* vb = reinterpret_cast<const uint2*>(g_vh + (size_t)src * 32 + j * 2);

        float part[4];
#pragma unroll
        for (int i = 0; i < 4; i++) {
            uint2 kr = kb[i * 4];
            float2 q0 = h2f(qv[i].x), q1 = h2f(qv[i].y);
            float2 k0 = h2f(kr.x),  k1 = h2f(kr.y);
            float2 p0 = h2f(pv[i].x), p1 = h2f(pv[i].y);
            part[i] = q0.x * k0.x + q0.y * k0.y + q1.x * k1.x + q1.y * k1.y
                    + p0.x * ea0.x + p0.y * ea0.y + p1.x * ea1.x + p1.y * ea1.y;
        }
        part[j] += rj;
#pragma unroll
        for (int off = 1; off < 4; off <<= 1) {
#pragma unroll
            for (int i = 0; i < 4; i++) part[i] += __shfl_xor_sync(gmask, part[i], off);
        }
        float ex[4];
#pragma unroll
        for (int i = 0; i < 4; i++) ex[i] = __expf(part[i] * 0.25f);

#pragma unroll
        for (int i = 0; i < 4; i++) {
            ad[i] += ex[i];
            uint2 vr = vb[i * 4];
            float2 v0 = h2f(vr.x), v1 = h2f(vr.y);
            at[i][0] += ex[i] * v0.x; at[i][1] += ex[i] * v0.y;
            at[i][2] += ex[i] * v1.x; at[i][3] += ex[i] * v1.y;
            as_[i][0] += ex[i] * ea0.x; as_[i][1] += ex[i] * ea0.y;
            as_[i][2] += ex[i] * ea1.x; as_[i][3] += ex[i] * ea1.y;
        }
    }

    // fused finalize: w = We_h^T s_h (s gathered across the quad), normalize, + skip
#pragma unroll
    for (int i = 0; i < 4; i++) {
        float w0 = 0.f, w1 = 0.f, w2 = 0.f, w3 = 0.f;
#pragma unroll
        for (int srcl = 0; srcl < 4; srcl++) {
#pragma unroll
            for (int cc = 0; cc < 4; cc++) {
                float sc = __shfl_sync(gmask, as_[i][cc], lbase + srcl);
                float4 ww = *reinterpret_cast<const float4*>(
                    &sWe[(srcl * 4 + cc) * 64 + i * 16 + j * 4]);
                w0 += sc * ww.x; w1 += sc * ww.y; w2 += sc * ww.z; w3 += sc * ww.w;
            }
        }
        float den = ad[i];
        float inv = 1.0f / (den + 1e-16f);
        int ch = i * 16 + j * 4;
        float4 sk = *reinterpret_cast<const float4*>(g_skip + (size_t)node * 64 + ch);
        float4 o;
        o.x = (at[i][0] + w0 + den * sbe[ch + 0]) * inv + sk.x;
        o.y = (at[i][1] + w1 + den * sbe[ch + 1]) * inv + sk.y;
        o.z = (at[i][2] + w2 + den * sbe[ch + 2]) * inv + sk.z;
        o.w = (at[i][3] + w3 + den * sbe[ch + 3]) * inv + sk.w;
        *reinterpret_cast<float4*>(g_t + (size_t)node * 64 + ch) = o;
    }
}

// ---------------- BN stats (into layer-indexed buffers) ----------------
__global__ void bn_stats_kernel(int n, int layer) {
    int tid = threadIdx.x;
    int c = tid & 63;
    int rowg = tid >> 6;
    float s = 0.0f, q = 0.0f;
    for (int r = blockIdx.x * 4 + rowg; r < n; r += gridDim.x * 4) {
        float v = g_t[(size_t)r * 64 + c];
        s += v; q += v * v;
    }
    __shared__ float ss[256], sq[256];
    ss[tid] = s; sq[tid] = q;
    __syncthreads();
    if (tid < 128) { ss[tid] += ss[tid + 128]; sq[tid] += sq[tid + 128]; }
    __syncthreads();
    if (tid < 64) {
        atomicAdd(&g_bnsum3[layer * 64 + tid], ss[tid] + ss[tid + 64]);
        atomicAdd(&g_bnsq3[layer * 64 + tid], sq[tid] + sq[tid + 64]);
    }
}

// ---------------- final BN apply + GELU + residual (layer 3 only) ----------------
__global__ void bn_apply_kernel(const float* __restrict__ gamma, const float* __restrict__ beta,
                                int layer, int n) {
    int idx = blockIdx.x * blockDim.x + threadIdx.x;
    if (idx >= n * 16) return;
    int c0 = (idx & 15) * 4;
    float invN = 1.0f / (float)n;
    float4 tv = reinterpret_cast<const float4*>(g_t)[idx];
    float4 hv = reinterpret_cast<const float4*>(g_h)[idx];
    float tt[4] = {tv.x, tv.y, tv.z, tv.w};
    float hh[4] = {hv.x, hv.y, hv.z, hv.w};
    float r[4];
#pragma unroll
    for (int k = 0; k < 4; k++) {
        int c = c0 + k;
        float mu = g_bnsum3[layer * 64 + c] * invN;
        float var = g_bnsq3[layer * 64 + c] * invN - mu * mu;
        float y = gamma[c] * (tt[k] - mu) * rsqrtf(var + 1e-5f) + beta[c];
        float gl = 0.5f * y * (1.0f + erff(y * 0.70710678118654752f));
        r[k] = gl + hh[k];
    }
    float4 o; o.x = r[0]; o.y = r[1]; o.z = r[2]; o.w = r[3];
    reinterpret_cast<float4*>(g_h)[idx] = o;
}

// ---------------- pooling ----------------
__global__ void clear_pool_kernel(int G) {
    int i = blockIdx.x * blockDim.x + threadIdx.x;
    if (i < G * 64) g_pool[i] = 0.0f;
    if (i < G) g_cnt[i] = 0.0f;
}

__global__ void pool_kernel(const int* __restrict__ batch, int n) {
    int idx = blockIdx.x * blockDim.x + threadIdx.x;
    if (idx >= n * 16) return;
    int node = idx >> 4, c4 = idx & 15;
    int g = batch[node];
    float4 v = reinterpret_cast<const float4*>(g_h)[idx];
    redAddV4(&g_pool[g * 64 + c4 * 4], v.x, v.y, v.z, v.w);
    if (c4 == 0) atomicAdd(&g_cnt[g], 1.0f);
}

// ---------------- regressor ----------------
__global__ void reg_kernel(const float* __restrict__ rw1, const float* __restrict__ rb1,
                           const float* __restrict__ rw2, const float* __restrict__ rb2,
                           float* __restrict__ out) {
    int g = blockIdx.x;
    int tid = threadIdx.x;  // 128 threads
    __shared__ float feat[128];
    __shared__ float hred[64];
    float invc = 1.0f / fmaxf(g_cnt[g], 1.0f);
    float s = g_pool[g * 64 + (tid & 63)];
    feat[tid] = (tid < 64) ? s * invc : s;
    __syncthreads();
    if (tid < 64) {
        float acc = rb1[tid];
#pragma unroll 8
        for (int i = 0; i < 128; i++) acc += feat[i] * rw1[i * 64 + tid];
        acc = fmaxf(acc, 0.0f);
        hred[tid] = acc * rw2[tid];
    }
    __syncthreads();
    if (tid < 32) {
        float v = hred[tid] + hred[tid + 32];
#pragma unroll
        for (int off = 16; off > 0; off >>= 1) v += __shfl_down_sync(0xffffffffu, v, off);
        if (tid == 0) out[g] = v + rb2[0];
    }
}

// ---------------- host orchestration ----------------
extern "C" void kernel_launch(void* const* d_in, const int* in_sizes, int n_in,
                              void* d_out, int out_size) {
    const float* x      = (const float*)d_in[0];
    const int*   ei     = (const int*)d_in[1];
    const float* eattr  = (const float*)d_in[2];
    const int*   batch  = (const int*)d_in[3];
    const float* node_w = (const float*)d_in[4];
    const float* node_b = (const float*)d_in[5];
    const float* Wq = (const float*)d_in[6];
    const float* bq = (const float*)d_in[7];
    const float* Wk = (const float*)d_in[8];
    const float* bk = (const float*)d_in[9];
    const float* Wv = (const float*)d_in[10];
    const float* bv = (const float*)d_in[11];
    const float* We = (const float*)d_in[12];
    const float* be = (const float*)d_in[13];
    const float* Ws = (const float*)d_in[14];
    const float* bs = (const float*)d_in[15];
    const float* gamma = (const float*)d_in[16];
    const float* beta  = (const float*)d_in[17];
    const float* rw1 = (const float*)d_in[18];
    const float* rb1 = (const float*)d_in[19];
    const float* rw2 = (const float*)d_in[20];
    const float* rb2 = (const float*)d_in[21];
    float* out = (float*)d_out;

    int n = in_sizes[0] / 32;   // nodes
    int e = in_sizes[2] / 16;   // edges
    int G = out_size;           // graphs
    int nb = divup(n, 1024);

    float* ph;
    cudaGetSymbolAddress((void**)&ph, g_h);

    lin32_kernel<<<divup(n, 128), 128>>>(x, node_w, node_b, ph, n);

    // Build dst-sorted edge stream + CSR rows + degree-sorted node permutation (once)
    hist_clear_kernel<<<divup(n, 256), 256>>>(n);
    hist_kernel<<<divup(e, 256), 256>>>(ei, e);
    scan1_kernel<<<nb, 1024>>>(n);
    scan2_kernel<<<1, 32>>>(nb);
    scan3_kernel<<<nb, 1024>>>(n);
    scatter_kernel<<<divup(e, 256), 256>>>(ei, eattr, e);
    deg_hist_kernel<<<divup(n, 256), 256>>>(n);
    deg_scan_kernel<<<1, 256>>>();
    deg_scatter_kernel<<<divup(n, 256), 256>>>(n);

    for (int l = 0; l < 3; l++) {
        const float* wq = Wq + (size_t)l * 64 * 64;
        const float* wk = Wk + (size_t)l * 64 * 64;
        const float* wv = Wv + (size_t)l * 64 * 64;
        const float* ws = Ws + (size_t)l * 64 * 64;
        const float* we = We + (size_t)l * 16 * 64;
        float* psum; float* psq;
        cudaGetSymbolAddress((void**)&psum, g_bnsum3);
        cudaGetSymbolAddress((void**)&psq, g_bnsq3);

        qkvs_kernel<<<divup(n, 64), 256>>>(wq, bq + l * 64, wk, bk + l * 64,
                                           wv, bv + l * 64, ws, bs + l * 64,
                                           we, be + l * 64,
                                           gamma + (l - 1) * 64, beta + (l - 1) * 64,
                                           psum + (l - 1) * 64, psq + (l - 1) * 64,
                                           (l > 0) ? 1 : 0, n);
        edge_agg_kernel<<<divup((long long)n * 4, 256), 256>>>(we, be + l * 64, n);
        bn_stats_kernel<<<2048, 256>>>(n, l);
    }
    bn_apply_kernel<<<divup((long long)n * 16, 256), 256>>>(gamma + 2 * 64, beta + 2 * 64, 2, n);

    clear_pool_kernel<<<divup((long long)G * 64, 256), 256>>>(G);
    pool_kernel<<<divup((long long)n * 16, 256), 256>>>(batch, n);
    reg_kernel<<<G, 128>>>(rw1, rb1, rw2, rb2, out);
}

// round 14
// speedup vs baseline: 1.0546x; 1.0546x over previous
#include <cuda_runtime.h>
#include <cuda_fp16.h>
#include <math.h>
#include <stdint.h>

#define NMAX 100000
#define EMAX 1000000
#define GMAXG 512

// ---------------- scratch (device globals; no allocation allowed) ----------------
__device__ float   g_h[NMAX * 64];        // residual stream
__device__ float   g_t[NMAX * 64];        // post-attention / pre-BN buffer
__device__ __half2 g_qh[NMAX * 32];       // q fp16
__device__ __half2 g_kh[NMAX * 32];       // k fp16
__device__ __half2 g_vh[NMAX * 32];       // v fp16
__device__ __half2 g_ph[NMAX * 32];       // p_h = We_h @ q_h fp16
__device__ float   g_r[NMAX * 4];         // r_h = q_h . be_h
__device__ float   g_skip[NMAX * 64];
__device__ float   g_bnsum3[192];         // per-layer BN sums (3 x 64)
__device__ float   g_bnsq3[192];
__device__ float   g_pool[GMAXG * 64];
__device__ float   g_cnt[GMAXG];
// CSR / sorted edge stream (built once per launch; edge list is layer-invariant)
__device__ int     g_cnt_n[NMAX];
__device__ int     g_row[NMAX + 1];
__device__ int     g_wp[NMAX];
__device__ int     g_bsum[128];
__device__ int     g_ssrc[EMAX];
__device__ __half2 g_seah[EMAX * 8];

static inline unsigned divup(long long a, int b) { return (unsigned)((a + b - 1) / b); }

__device__ __forceinline__ void redAddV4(float* addr, float a, float b, float c, float d) {
    asm volatile("red.global.add.v4.f32 [%0], {%1,%2,%3,%4};"
                 :: "l"(addr), "f"(a), "f"(b), "f"(c), "f"(d) : "memory");
}
__device__ __forceinline__ float2 h2f(unsigned u) {
    return __half22float2(*reinterpret_cast<const __half2*>(&u));
}
__device__ __forceinline__ unsigned f2tf32(float x) {
    unsigned r;
    asm("cvt.rna.tf32.f32 %0, %1;" : "=r"(r) : "f"(x));
    return r;
}
__device__ __forceinline__ void mma_tf32(float* d, const unsigned* a, unsigned b0, unsigned b1) {
    asm volatile(
        "mma.sync.aligned.m16n8k8.row.col.f32.tf32.tf32.f32 "
        "{%0,%1,%2,%3}, {%4,%5,%6,%7}, {%8,%9}, {%0,%1,%2,%3};"
        : "+f"(d[0]), "+f"(d[1]), "+f"(d[2]), "+f"(d[3])
        : "r"(a[0]), "r"(a[1]), "r"(a[2]), "r"(a[3]), "r"(b0), "r"(b1));
}

// ---------------- initial node linear: out[n,64] = in[n,32] @ W[32,64] + b ----------------
__global__ void lin32_kernel(const float* __restrict__ in, const float* __restrict__ W,
                             const float* __restrict__ bias, float* __restrict__ out, int n) {
    __shared__ float sW[32 * 64];
    __shared__ float sb[64];
    for (int i = threadIdx.x; i < 32 * 64; i += blockDim.x) sW[i] = W[i];
    if (threadIdx.x < 64) sb[threadIdx.x] = bias[threadIdx.x];
    __syncthreads();
    int node = blockIdx.x * blockDim.x + threadIdx.x;
    if (node >= n) return;
    float4 acc[16];
#pragma unroll
    for (int j = 0; j < 16; j++) {
        acc[j].x = sb[4 * j + 0]; acc[j].y = sb[4 * j + 1];
        acc[j].z = sb[4 * j + 2]; acc[j].w = sb[4 * j + 3];
    }
    const float4* inp = reinterpret_cast<const float4*>(in + (size_t)node * 32);
#pragma unroll
    for (int c = 0; c < 8; c++) {
        float4 x4 = inp[c];
        float xs[4] = {x4.x, x4.y, x4.z, x4.w};
#pragma unroll
        for (int kk = 0; kk < 4; kk++) {
            float x = xs[kk];
            const float4* wr = reinterpret_cast<const float4*>(&sW[(c * 4 + kk) * 64]);
#pragma unroll
            for (int j = 0; j < 16; j++) {
                float4 w = wr[j];
                acc[j].x += x * w.x; acc[j].y += x * w.y;
                acc[j].z += x * w.z; acc[j].w += x * w.w;
            }
        }
    }
    float4* op = reinterpret_cast<float4*>(out + (size_t)node * 64);
#pragma unroll
    for (int j = 0; j < 16; j++) op[j] = acc[j];
}

// ---------------- CSR build (once per launch) ----------------
__global__ void hist_clear_kernel(int n, int G) {
    int i = blockIdx.x * blockDim.x + threadIdx.x;
    if (i < n) g_cnt_n[i] = 0;
    if (i < 192) { g_bnsum3[i] = 0.0f; g_bnsq3[i] = 0.0f; }
    if (i < G * 64) g_pool[i] = 0.0f;
    if (i < G) g_cnt[i] = 0.0f;
}
__global__ void hist_kernel(const int* __restrict__ ei, int e) {
    int i = blockIdx.x * blockDim.x + threadIdx.x;
    if (i < e) atomicAdd(&g_cnt_n[ei[e + i]], 1);
}
__global__ void scan1_kernel(int n) {
    __shared__ int sm[1024];
    int i = blockIdx.x * 1024 + threadIdx.x;
    int v = (i < n) ? g_cnt_n[i] : 0;
    sm[threadIdx.x] = v;
    __syncthreads();
    for (int off = 1; off < 1024; off <<= 1) {
        int t = (threadIdx.x >= off) ? sm[threadIdx.x - off] : 0;
        __syncthreads();
        sm[threadIdx.x] += t;
        __syncthreads();
    }
    if (i < n) g_row[i + 1] = sm[threadIdx.x];
    if (threadIdx.x == 1023) g_bsum[blockIdx.x] = sm[1023];
}
__global__ void scan2_kernel(int nb) {
    if (threadIdx.x == 0) {
        int acc = 0;
        for (int b = 0; b < nb; b++) { int t = g_bsum[b]; g_bsum[b] = acc; acc += t; }
    }
}
__global__ void scan3_kernel(int n) {
    int i = blockIdx.x * 1024 + threadIdx.x;
    if (i < n) {
        int incl = g_row[i + 1] + g_bsum[blockIdx.x];
        g_row[i + 1] = incl;
        g_wp[i] = incl - g_cnt_n[i];
    }
    if (i == 0) g_row[0] = 0;
}
__global__ void scatter_kernel(const int* __restrict__ ei, const float* __restrict__ eattr, int e) {
    int eid = blockIdx.x * 256 + threadIdx.x;
    if (eid >= e) return;
    int dst = ei[e + eid];
    int pos = atomicAdd(&g_wp[dst], 1);
    g_ssrc[pos] = ei[eid];
    const float4* ea = reinterpret_cast<const float4*>(eattr + (size_t)eid * 16);
    __half2 hp[8];
#pragma unroll
    for (int jj = 0; jj < 4; jj++) {
        float4 v = ea[jj];
        hp[2 * jj]     = __floats2half2_rn(v.x, v.y);
        hp[2 * jj + 1] = __floats2half2_rn(v.z, v.w);
    }
    uint4* dp = reinterpret_cast<uint4*>(g_seah + (size_t)pos * 8);
    dp[0] = *reinterpret_cast<uint4*>(&hp[0]);
    dp[1] = *reinterpret_cast<uint4*>(&hp[4]);
}

// ---------------- fused q/k/v/skip (tf32 mma) + p/r + optional BN/GELU/residual on input ----------------
// block = 256 threads (8 warps) = 64 nodes.
#define XS_STRIDE 68
#define SW_STRIDE 72
__global__ void qkvs_kernel(const float* __restrict__ Wq, const float* __restrict__ bq,
                            const float* __restrict__ Wk, const float* __restrict__ bk,
                            const float* __restrict__ Wv, const float* __restrict__ bv,
                            const float* __restrict__ Ws, const float* __restrict__ bs,
                            const float* __restrict__ We, const float* __restrict__ be,
                            const float* __restrict__ gamma, const float* __restrict__ beta,
                            const float* __restrict__ bnsum, const float* __restrict__ bnsq,
                            int apply_bn, int n) {
    __shared__ float xs[64 * XS_STRIDE];
    __shared__ float sW[64 * SW_STRIDE];
    __shared__ float sb[64];
    __shared__ float sWe[16 * 64];
    __shared__ float sbe[64];
    __shared__ __half qbuf[64 * 64];
    const int tid = threadIdx.x;
    const int base = blockIdx.x * 64;
    const float invN = 1.0f / (float)n;

    // input tile: either plain g_h, or h_new = gelu(bn(g_t)) + g_h (fused bn_apply),
    // in which case g_h is updated too.
    for (int idx = tid; idx < 64 * 16; idx += 256) {
        int nl = idx >> 4, kk = idx & 15;
        int gn = base + nl;
        if (gn < n) {
            float4 h4 = reinterpret_cast<const float4*>(g_h)[gn * 16 + kk];
            if (apply_bn) {
                float4 t4 = reinterpret_cast<const float4*>(g_t)[gn * 16 + kk];
                float tt[4] = {t4.x, t4.y, t4.z, t4.w};
                float hh[4] = {h4.x, h4.y, h4.z, h4.w};
                float r[4];
#pragma unroll
                for (int k = 0; k < 4; k++) {
                    int c = kk * 4 + k;
                    float mu = bnsum[c] * invN;
                    float var = bnsq[c] * invN - mu * mu;
                    float y = gamma[c] * (tt[k] - mu) * rsqrtf(var + 1e-5f) + beta[c];
                    float gl = 0.5f * y * (1.0f + erff(y * 0.70710678118654752f));
                    r[k] = gl + hh[k];
                }
                h4.x = r[0]; h4.y = r[1]; h4.z = r[2]; h4.w = r[3];
                reinterpret_cast<float4*>(g_h)[gn * 16 + kk] = h4;
            }
            float* p = &xs[nl * XS_STRIDE + kk * 4];
            p[0] = h4.x; p[1] = h4.y; p[2] = h4.z; p[3] = h4.w;
        }
    }
    for (int i = tid; i < 1024; i += 256) sWe[i] = We[i];
    if (tid < 64) sbe[tid] = be[tid];

    const float* Wm[4] = {Wq, Wk, Wv, Ws};
    const float* bm[4] = {bq, bk, bv, bs};

    const int warp = tid >> 5, lane = tid & 31;
    const int g4 = warp >> 1;
    const int chalf = warp & 1;
    const int grp = lane >> 2;
    const int qd = lane & 3;
    const int nl = tid & 63;
    const int quart = tid >> 6;
    const int gn = base + nl;

    for (int m = 0; m < 4; m++) {
        __syncthreads();
        {
            const float* wsrc = Wm[m];
            for (int i = tid; i < 4096; i += 256) {
                sW[(i >> 6) * SW_STRIDE + (i & 63)] = __uint_as_float(f2tf32(wsrc[i]));
            }
            if (tid < 64) sb[tid] = bm[m][tid];
        }
        __syncthreads();

        float acc[4][4];
#pragma unroll
        for (int t = 0; t < 4; t++)
#pragma unroll
            for (int d = 0; d < 4; d++) acc[t][d] = 0.0f;

#pragma unroll
        for (int ks = 0; ks < 8; ks++) {
            unsigned a[4];
            const float* xr = &xs[(g4 * 16 + grp) * XS_STRIDE + ks * 8 + qd];
            a[0] = f2tf32(xr[0]);
            a[2] = f2tf32(xr[4]);
            a[1] = f2tf32(xr[8 * XS_STRIDE]);
            a[3] = f2tf32(xr[8 * XS_STRIDE + 4]);
#pragma unroll
            for (int t = 0; t < 4; t++) {
                int cb = chalf * 32 + t * 8;
                unsigned b0 = __float_as_uint(sW[(ks * 8 + qd) * SW_STRIDE + cb + grp]);
                unsigned b1 = __float_as_uint(sW[(ks * 8 + qd + 4) * SW_STRIDE + cb + grp]);
                mma_tf32(acc[t], a, b0, b1);
            }
        }

        int r0 = g4 * 16 + grp;
        if (m == 3) {
#pragma unroll
            for (int t = 0; t < 4; t++) {
                int col = chalf * 32 + t * 8 + qd * 2;
                if (base + r0 < n) {
                    float2 o; o.x = acc[t][0] + sb[col]; o.y = acc[t][1] + sb[col + 1];
                    *reinterpret_cast<float2*>(g_skip + (size_t)(base + r0) * 64 + col) = o;
                }
                if (base + r0 + 8 < n) {
                    float2 o; o.x = acc[t][2] + sb[col]; o.y = acc[t][3] + sb[col + 1];
                    *reinterpret_cast<float2*>(g_skip + (size_t)(base + r0 + 8) * 64 + col) = o;
                }
            }
        } else {
#pragma unroll
            for (int t = 0; t < 4; t++) {
                int col = chalf * 32 + t * 8 + qd * 2;
                __half2 hlo = __floats2half2_rn(acc[t][0] + sb[col], acc[t][1] + sb[col + 1]);
                __half2 hhi = __floats2half2_rn(acc[t][2] + sb[col], acc[t][3] + sb[col + 1]);
                if (m == 0) {
                    *reinterpret_cast<__half2*>(&qbuf[r0 * 64 + col]) = hlo;
                    *reinterpret_cast<__half2*>(&qbuf[(r0 + 8) * 64 + col]) = hhi;
                } else {
                    __half2* dst = (m == 1) ? g_kh : g_vh;
                    if (base + r0 < n)     dst[(size_t)(base + r0) * 32 + (col >> 1)] = hlo;
                    if (base + r0 + 8 < n) dst[(size_t)(base + r0 + 8) * 32 + (col >> 1)] = hhi;
                }
            }
            if (m == 0) {
                __syncthreads();
                if (gn < n) {
                    uint4 u0 = *reinterpret_cast<const uint4*>(&qbuf[nl * 64 + quart * 16]);
                    uint4 u1 = *reinterpret_cast<const uint4*>(&qbuf[nl * 64 + quart * 16 + 8]);
                    uint4* qp = reinterpret_cast<uint4*>(g_qh + (size_t)gn * 32 + quart * 8);
                    qp[0] = u0; qp[1] = u1;
                    float qv[16];
                    {
                        const unsigned* uw = reinterpret_cast<const unsigned*>(&u0);
#pragma unroll
                        for (int j = 0; j < 4; j++) {
                            float2 f = h2f(uw[j]); qv[2 * j] = f.x; qv[2 * j + 1] = f.y;
                        }
                        const unsigned* uw1 = reinterpret_cast<const unsigned*>(&u1);
#pragma unroll
                        for (int j = 0; j < 4; j++) {
                            float2 f = h2f(uw1[j]); qv[8 + 2 * j] = f.x; qv[9 + 2 * j] = f.y;
                        }
                    }
                    float pc[16];
#pragma unroll
                    for (int c = 0; c < 16; c++) {
                        const float4* wr = reinterpret_cast<const float4*>(&sWe[c * 64 + quart * 16]);
                        float s = 0.0f;
#pragma unroll
                        for (int j = 0; j < 4; j++) {
                            float4 w = wr[j];
                            s += w.x * qv[4 * j] + w.y * qv[4 * j + 1]
                               + w.z * qv[4 * j + 2] + w.w * qv[4 * j + 3];
                        }
                        pc[c] = s;
                    }
                    float rr = 0.0f;
#pragma unroll
                    for (int d = 0; d < 16; d++) rr += sbe[quart * 16 + d] * qv[d];
                    __half2 hp[8];
#pragma unroll
                    for (int j = 0; j < 8; j++) hp[j] = __floats2half2_rn(pc[2 * j], pc[2 * j + 1]);
                    uint4* pp = reinterpret_cast<uint4*>(g_ph + (size_t)gn * 32 + quart * 8);
                    pp[0] = *reinterpret_cast<uint4*>(&hp[0]);
                    pp[1] = *reinterpret_cast<uint4*>(&hp[4]);
                    g_r[gn * 4 + quart] = rr;
                }
            }
        }
    }
}

// ---------------- edge aggregation + finalize, fused; zero atomics; natural node order ----------------
__global__ void edge_agg_kernel(const float* __restrict__ We, const float* __restrict__ be, int n) {
    __shared__ float sWe[16 * 64];
    __shared__ float sbe[64];
    const int tid = threadIdx.x;
    for (int i = tid; i < 1024; i += 256) sWe[i] = We[i];
    if (tid < 64) sbe[tid] = be[tid];
    __syncthreads();

    int idx = blockIdx.x * 256 + tid;   // (node, j)
    if (idx >= n * 4) return;
    const int node = idx >> 2;
    const int j = idx & 3;
    const unsigned lane = tid & 31;
    const unsigned gmask = 0xFu << (lane & 28);
    const int lbase = lane & 28;

    const uint2* qb = reinterpret_cast<const uint2*>(g_qh + (size_t)node * 32 + j * 2);
    const uint2* pb = reinterpret_cast<const uint2*>(g_ph + (size_t)node * 32 + j * 2);
    uint2 qv[4], pv[4];
#pragma unroll
    for (int i = 0; i < 4; i++) { qv[i] = qb[i * 4]; pv[i] = pb[i * 4]; }
    const float rj = g_r[node * 4 + j];

    const int rs = g_row[node], re = g_row[node + 1];
    float at[4][4], as_[4][4], ad[4];
#pragma unroll
    for (int i = 0; i < 4; i++) {
        ad[i] = 0.0f;
#pragma unroll
        for (int d = 0; d < 4; d++) { at[i][d] = 0.0f; as_[i][d] = 0.0f; }
    }

    for (int pos = rs; pos < re; pos++) {
        int src = g_ssrc[pos];
        uint2 eaw = *reinterpret_cast<const uint2*>(g_seah + (size_t)pos * 8 + j * 2);
        float2 ea0 = h2f(eaw.x), ea1 = h2f(eaw.y);
        const uint2* kb = reinterpret_cast<const uint2*>(g_kh + (size_t)src * 32 + j * 2);
        const uint2* vb = reinterpret_cast<const uint2*>(g_vh + (size_t)src * 32 + j * 2);

        float part[4];
#pragma unroll
        for (int i = 0; i < 4; i++) {
            uint2 kr = kb[i * 4];
            float2 q0 = h2f(qv[i].x), q1 = h2f(qv[i].y);
            float2 k0 = h2f(kr.x),  k1 = h2f(kr.y);
            float2 p0 = h2f(pv[i].x), p1 = h2f(pv[i].y);
            part[i] = q0.x * k0.x + q0.y * k0.y + q1.x * k1.x + q1.y * k1.y
                    + p0.x * ea0.x + p0.y * ea0.y + p1.x * ea1.x + p1.y * ea1.y;
        }
        part[j] += rj;
#pragma unroll
        for (int off = 1; off < 4; off <<= 1) {
#pragma unroll
            for (int i = 0; i < 4; i++) part[i] += __shfl_xor_sync(gmask, part[i], off);
        }
        float ex[4];
#pragma unroll
        for (int i = 0; i < 4; i++) ex[i] = __expf(part[i] * 0.25f);

#pragma unroll
        for (int i = 0; i < 4; i++) {
            ad[i] += ex[i];
            uint2 vr = vb[i * 4];
            float2 v0 = h2f(vr.x), v1 = h2f(vr.y);
            at[i][0] += ex[i] * v0.x; at[i][1] += ex[i] * v0.y;
            at[i][2] += ex[i] * v1.x; at[i][3] += ex[i] * v1.y;
            as_[i][0] += ex[i] * ea0.x; as_[i][1] += ex[i] * ea0.y;
            as_[i][2] += ex[i] * ea1.x; as_[i][3] += ex[i] * ea1.y;
        }
    }

    // fused finalize: w = We_h^T s_h (s gathered across the quad), normalize, + skip
#pragma unroll
    for (int i = 0; i < 4; i++) {
        float w0 = 0.f, w1 = 0.f, w2 = 0.f, w3 = 0.f;
#pragma unroll
        for (int srcl = 0; srcl < 4; srcl++) {
#pragma unroll
            for (int cc = 0; cc < 4; cc++) {
                float sc = __shfl_sync(gmask, as_[i][cc], lbase + srcl);
                float4 ww = *reinterpret_cast<const float4*>(
                    &sWe[(srcl * 4 + cc) * 64 + i * 16 + j * 4]);
                w0 += sc * ww.x; w1 += sc * ww.y; w2 += sc * ww.z; w3 += sc * ww.w;
            }
        }
        float den = ad[i];
        float inv = 1.0f / (den + 1e-16f);
        int ch = i * 16 + j * 4;
        float4 sk = *reinterpret_cast<const float4*>(g_skip + (size_t)node * 64 + ch);
        float4 o;
        o.x = (at[i][0] + w0 + den * sbe[ch + 0]) * inv + sk.x;
        o.y = (at[i][1] + w1 + den * sbe[ch + 1]) * inv + sk.y;
        o.z = (at[i][2] + w2 + den * sbe[ch + 2]) * inv + sk.z;
        o.w = (at[i][3] + w3 + den * sbe[ch + 3]) * inv + sk.w;
        *reinterpret_cast<float4*>(g_t + (size_t)node * 64 + ch) = o;
    }
}

// ---------------- BN stats (into layer-indexed buffers) ----------------
__global__ void bn_stats_kernel(int n, int layer) {
    int tid = threadIdx.x;
    int c = tid & 63;
    int rowg = tid >> 6;
    float s = 0.0f, q = 0.0f;
    for (int r = blockIdx.x * 4 + rowg; r < n; r += gridDim.x * 4) {
        float v = g_t[(size_t)r * 64 + c];
        s += v; q += v * v;
    }
    __shared__ float ss[256], sq[256];
    ss[tid] = s; sq[tid] = q;
    __syncthreads();
    if (tid < 128) { ss[tid] += ss[tid + 128]; sq[tid] += sq[tid + 128]; }
    __syncthreads();
    if (tid < 64) {
        atomicAdd(&g_bnsum3[layer * 64 + tid], ss[tid] + ss[tid + 64]);
        atomicAdd(&g_bnsq3[layer * 64 + tid], sq[tid] + sq[tid + 64]);
    }
}

// ---------------- final BN apply + GELU + residual + fused pooling (layer 3 only) ----------------
__global__ void bn_apply_pool_kernel(const float* __restrict__ gamma, const float* __restrict__ beta,
                                     const int* __restrict__ batch, int layer, int n) {
    int idx = blockIdx.x * blockDim.x + threadIdx.x;
    if (idx >= n * 16) return;
    int node = idx >> 4;
    int c0 = (idx & 15) * 4;
    float invN = 1.0f / (float)n;
    float4 tv = reinterpret_cast<const float4*>(g_t)[idx];
    float4 hv = reinterpret_cast<const float4*>(g_h)[idx];
    float tt[4] = {tv.x, tv.y, tv.z, tv.w};
    float hh[4] = {hv.x, hv.y, hv.z, hv.w};
    float r[4];
#pragma unroll
    for (int k = 0; k < 4; k++) {
        int c = c0 + k;
        float mu = g_bnsum3[layer * 64 + c] * invN;
        float var = g_bnsq3[layer * 64 + c] * invN - mu * mu;
        float y = gamma[c] * (tt[k] - mu) * rsqrtf(var + 1e-5f) + beta[c];
        float gl = 0.5f * y * (1.0f + erff(y * 0.70710678118654752f));
        r[k] = gl + hh[k];
    }
    int g = batch[node];
    redAddV4(&g_pool[g * 64 + c0], r[0], r[1], r[2], r[3]);
    if (c0 == 0) atomicAdd(&g_cnt[g], 1.0f);
}

// ---------------- regressor ----------------
__global__ void reg_kernel(const float* __restrict__ rw1, const float* __restrict__ rb1,
                           const float* __restrict__ rw2, const float* __restrict__ rb2,
                           float* __restrict__ out) {
    int g = blockIdx.x;
    int tid = threadIdx.x;  // 128 threads
    __shared__ float feat[128];
    __shared__ float hred[64];
    float invc = 1.0f / fmaxf(g_cnt[g], 1.0f);
    float s = g_pool[g * 64 + (tid & 63)];
    feat[tid] = (tid < 64) ? s * invc : s;
    __syncthreads();
    if (tid < 64) {
        float acc = rb1[tid];
#pragma unroll 8
        for (int i = 0; i < 128; i++) acc += feat[i] * rw1[i * 64 + tid];
        acc = fmaxf(acc, 0.0f);
        hred[tid] = acc * rw2[tid];
    }
    __syncthreads();
    if (tid < 32) {
        float v = hred[tid] + hred[tid + 32];
#pragma unroll
        for (int off = 16; off > 0; off >>= 1) v += __shfl_down_sync(0xffffffffu, v, off);
        if (tid == 0) out[g] = v + rb2[0];
    }
}

// ---------------- host orchestration ----------------
extern "C" void kernel_launch(void* const* d_in, const int* in_sizes, int n_in,
                              void* d_out, int out_size) {
    const float* x      = (const float*)d_in[0];
    const int*   ei     = (const int*)d_in[1];
    const float* eattr  = (const float*)d_in[2];
    const int*   batch  = (const int*)d_in[3];
    const float* node_w = (const float*)d_in[4];
    const float* node_b = (const float*)d_in[5];
    const float* Wq = (const float*)d_in[6];
    const float* bq = (const float*)d_in[7];
    const float* Wk = (const float*)d_in[8];
    const float* bk = (const float*)d_in[9];
    const float* Wv = (const float*)d_in[10];
    const float* bv = (const float*)d_in[11];
    const float* We = (const float*)d_in[12];
    const float* be = (const float*)d_in[13];
    const float* Ws = (const float*)d_in[14];
    const float* bs = (const float*)d_in[15];
    const float* gamma = (const float*)d_in[16];
    const float* beta  = (const float*)d_in[17];
    const float* rw1 = (const float*)d_in[18];
    const float* rb1 = (const float*)d_in[19];
    const float* rw2 = (const float*)d_in[20];
    const float* rb2 = (const float*)d_in[21];
    float* out = (float*)d_out;

    int n = in_sizes[0] / 32;   // nodes
    int e = in_sizes[2] / 16;   // edges
    int G = out_size;           // graphs
    int nb = divup(n, 1024);

    float* ph;
    cudaGetSymbolAddress((void**)&ph, g_h);

    lin32_kernel<<<divup(n, 128), 128>>>(x, node_w, node_b, ph, n);

    // Build dst-sorted edge stream + CSR rows (once; reused by all 3 layers)
    hist_clear_kernel<<<divup(n, 256), 256>>>(n, G);
    hist_kernel<<<divup(e, 256), 256>>>(ei, e);
    scan1_kernel<<<nb, 1024>>>(n);
    scan2_kernel<<<1, 32>>>(nb);
    scan3_kernel<<<nb, 1024>>>(n);
    scatter_kernel<<<divup(e, 256), 256>>>(ei, eattr, e);

    float* psum; float* psq;
    cudaGetSymbolAddress((void**)&psum, g_bnsum3);
    cudaGetSymbolAddress((void**)&psq, g_bnsq3);

    for (int l = 0; l < 3; l++) {
        const float* wq = Wq + (size_t)l * 64 * 64;
        const float* wk = Wk + (size_t)l * 64 * 64;
        const float* wv = Wv + (size_t)l * 64 * 64;
        const float* ws = Ws + (size_t)l * 64 * 64;
        const float* we = We + (size_t)l * 16 * 64;

        qkvs_kernel<<<divup(n, 64), 256>>>(wq, bq + l * 64, wk, bk + l * 64,
                                           wv, bv + l * 64, ws, bs + l * 64,
                                           we, be + l * 64,
                                           gamma + (l - 1) * 64, beta + (l - 1) * 64,
                                           psum + (l - 1) * 64, psq + (l - 1) * 64,
                                           (l > 0) ? 1 : 0, n);
        edge_agg_kernel<<<divup((long long)n * 4, 256), 256>>>(we, be + l * 64, n);
        bn_stats_kernel<<<2048, 256>>>(n, l);
    }
    bn_apply_pool_kernel<<<divup((long long)n * 16, 256), 256>>>(gamma + 2 * 64, beta + 2 * 64,
                                                                 batch, 2, n);
    reg_kernel<<<G, 128>>>(rw1, rb1, rw2, rb2, out);
}

// round 15
// speedup vs baseline: 1.0800x; 1.0241x over previous
#include <cuda_runtime.h>
#include <cuda_fp16.h>
#include <math.h>
#include <stdint.h>

#define NMAX 100000
#define EMAX 1000000
#define GMAXG 512

// ---------------- scratch (device globals; no allocation allowed) ----------------
__device__ float   g_h[NMAX * 64];        // residual stream
__device__ float   g_t[NMAX * 64];        // post-attention / pre-BN buffer
__device__ __half2 g_qh[NMAX * 32];       // q fp16
__device__ __half2 g_kh[NMAX * 32];       // k fp16
__device__ __half2 g_vh[NMAX * 32];       // v fp16
__device__ __half2 g_ph[NMAX * 32];       // p_h = We_h @ q_h fp16
__device__ float   g_r[NMAX * 4];         // r_h = q_h . be_h
__device__ float   g_skip[NMAX * 64];
__device__ float   g_bnsum3[192];         // per-layer BN sums (3 x 64)
__device__ float   g_bnsq3[192];
__device__ float   g_pool[GMAXG * 64];
__device__ float   g_cnt[GMAXG];
// CSR / sorted edge stream (built once per launch; edge list is layer-invariant)
__device__ int     g_cnt_n[NMAX];
__device__ int     g_row[NMAX + 1];
__device__ int     g_wp[NMAX];
__device__ int     g_bsum[128];
__device__ int     g_ssrc[EMAX];
__device__ __half2 g_seah[EMAX * 8];

static inline unsigned divup(long long a, int b) { return (unsigned)((a + b - 1) / b); }

__device__ __forceinline__ void redAddV4(float* addr, float a, float b, float c, float d) {
    asm volatile("red.global.add.v4.f32 [%0], {%1,%2,%3,%4};"
                 :: "l"(addr), "f"(a), "f"(b), "f"(c), "f"(d) : "memory");
}
__device__ __forceinline__ float2 h2f(unsigned u) {
    return __half22float2(*reinterpret_cast<const __half2*>(&u));
}
__device__ __forceinline__ unsigned f2tf32(float x) {
    unsigned r;
    asm("cvt.rna.tf32.f32 %0, %1;" : "=r"(r) : "f"(x));
    return r;
}
__device__ __forceinline__ void mma_tf32(float* d, const unsigned* a, unsigned b0, unsigned b1) {
    asm volatile(
        "mma.sync.aligned.m16n8k8.row.col.f32.tf32.tf32.f32 "
        "{%0,%1,%2,%3}, {%4,%5,%6,%7}, {%8,%9}, {%0,%1,%2,%3};"
        : "+f"(d[0]), "+f"(d[1]), "+f"(d[2]), "+f"(d[3])
        : "r"(a[0]), "r"(a[1]), "r"(a[2]), "r"(a[3]), "r"(b0), "r"(b1));
}
__device__ __forceinline__ void unpack16(uint4 u0, uint4 u1, float* f) {
    const unsigned* w0 = reinterpret_cast<const unsigned*>(&u0);
    const unsigned* w1 = reinterpret_cast<const unsigned*>(&u1);
#pragma unroll
    for (int i = 0; i < 4; i++) {
        float2 a = h2f(w0[i]); f[2 * i] = a.x; f[2 * i + 1] = a.y;
        float2 b = h2f(w1[i]); f[8 + 2 * i] = b.x; f[9 + 2 * i] = b.y;
    }
}

// ---------------- initial node linear: out[n,64] = in[n,32] @ W[32,64] + b ----------------
__global__ void lin32_kernel(const float* __restrict__ in, const float* __restrict__ W,
                             const float* __restrict__ bias, float* __restrict__ out, int n) {
    __shared__ float sW[32 * 64];
    __shared__ float sb[64];
    for (int i = threadIdx.x; i < 32 * 64; i += blockDim.x) sW[i] = W[i];
    if (threadIdx.x < 64) sb[threadIdx.x] = bias[threadIdx.x];
    __syncthreads();
    int node = blockIdx.x * blockDim.x + threadIdx.x;
    if (node >= n) return;
    float4 acc[16];
#pragma unroll
    for (int j = 0; j < 16; j++) {
        acc[j].x = sb[4 * j + 0]; acc[j].y = sb[4 * j + 1];
        acc[j].z = sb[4 * j + 2]; acc[j].w = sb[4 * j + 3];
    }
    const float4* inp = reinterpret_cast<const float4*>(in + (size_t)node * 32);
#pragma unroll
    for (int c = 0; c < 8; c++) {
        float4 x4 = inp[c];
        float xs[4] = {x4.x, x4.y, x4.z, x4.w};
#pragma unroll
        for (int kk = 0; kk < 4; kk++) {
            float x = xs[kk];
            const float4* wr = reinterpret_cast<const float4*>(&sW[(c * 4 + kk) * 64]);
#pragma unroll
            for (int j = 0; j < 16; j++) {
                float4 w = wr[j];
                acc[j].x += x * w.x; acc[j].y += x * w.y;
                acc[j].z += x * w.z; acc[j].w += x * w.w;
            }
        }
    }
    float4* op = reinterpret_cast<float4*>(out + (size_t)node * 64);
#pragma unroll
    for (int j = 0; j < 16; j++) op[j] = acc[j];
}

// ---------------- CSR build (once per launch) ----------------
__global__ void hist_clear_kernel(int n, int G) {
    int i = blockIdx.x * blockDim.x + threadIdx.x;
    if (i < n) g_cnt_n[i] = 0;
    if (i < 192) { g_bnsum3[i] = 0.0f; g_bnsq3[i] = 0.0f; }
    if (i < G * 64) g_pool[i] = 0.0f;
    if (i < G) g_cnt[i] = 0.0f;
}
__global__ void hist_kernel(const int* __restrict__ ei, int e) {
    int i = blockIdx.x * blockDim.x + threadIdx.x;
    if (i < e) atomicAdd(&g_cnt_n[ei[e + i]], 1);
}
__global__ void scan1_kernel(int n) {
    __shared__ int sm[1024];
    int i = blockIdx.x * 1024 + threadIdx.x;
    int v = (i < n) ? g_cnt_n[i] : 0;
    sm[threadIdx.x] = v;
    __syncthreads();
    for (int off = 1; off < 1024; off <<= 1) {
        int t = (threadIdx.x >= off) ? sm[threadIdx.x - off] : 0;
        __syncthreads();
        sm[threadIdx.x] += t;
        __syncthreads();
    }
    if (i < n) g_row[i + 1] = sm[threadIdx.x];
    if (threadIdx.x == 1023) g_bsum[blockIdx.x] = sm[1023];
}
__global__ void scan2_kernel(int nb) {
    if (threadIdx.x == 0) {
        int acc = 0;
        for (int b = 0; b < nb; b++) { int t = g_bsum[b]; g_bsum[b] = acc; acc += t; }
    }
}
__global__ void scan3_kernel(int n) {
    int i = blockIdx.x * 1024 + threadIdx.x;
    if (i < n) {
        int incl = g_row[i + 1] + g_bsum[blockIdx.x];
        g_row[i + 1] = incl;
        g_wp[i] = incl - g_cnt_n[i];
    }
    if (i == 0) g_row[0] = 0;
}
__global__ void scatter_kernel(const int* __restrict__ ei, const float* __restrict__ eattr, int e) {
    int eid = blockIdx.x * 256 + threadIdx.x;
    if (eid >= e) return;
    int dst = ei[e + eid];
    int pos = atomicAdd(&g_wp[dst], 1);
    g_ssrc[pos] = ei[eid];
    const float4* ea = reinterpret_cast<const float4*>(eattr + (size_t)eid * 16);
    __half2 hp[8];
#pragma unroll
    for (int jj = 0; jj < 4; jj++) {
        float4 v = ea[jj];
        hp[2 * jj]     = __floats2half2_rn(v.x, v.y);
        hp[2 * jj + 1] = __floats2half2_rn(v.z, v.w);
    }
    uint4* dp = reinterpret_cast<uint4*>(g_seah + (size_t)pos * 8);
    dp[0] = *reinterpret_cast<uint4*>(&hp[0]);
    dp[1] = *reinterpret_cast<uint4*>(&hp[4]);
}

// ---------------- fused q/k/v/skip (tf32 mma) + p/r + optional BN/GELU/residual on input ----------------
// block = 256 threads (8 warps) = 64 nodes.
#define XS_STRIDE 68
#define SW_STRIDE 72
__global__ void qkvs_kernel(const float* __restrict__ Wq, const float* __restrict__ bq,
                            const float* __restrict__ Wk, const float* __restrict__ bk,
                            const float* __restrict__ Wv, const float* __restrict__ bv,
                            const float* __restrict__ Ws, const float* __restrict__ bs,
                            const float* __restrict__ We, const float* __restrict__ be,
                            const float* __restrict__ gamma, const float* __restrict__ beta,
                            const float* __restrict__ bnsum, const float* __restrict__ bnsq,
                            int apply_bn, int n) {
    __shared__ float xs[64 * XS_STRIDE];
    __shared__ float sW[64 * SW_STRIDE];
    __shared__ float sb[64];
    __shared__ float sWe[16 * 64];
    __shared__ float sbe[64];
    __shared__ __half qbuf[64 * 64];
    const int tid = threadIdx.x;
    const int base = blockIdx.x * 64;
    const float invN = 1.0f / (float)n;

    for (int idx = tid; idx < 64 * 16; idx += 256) {
        int nl = idx >> 4, kk = idx & 15;
        int gn = base + nl;
        if (gn < n) {
            float4 h4 = reinterpret_cast<const float4*>(g_h)[gn * 16 + kk];
            if (apply_bn) {
                float4 t4 = reinterpret_cast<const float4*>(g_t)[gn * 16 + kk];
                float tt[4] = {t4.x, t4.y, t4.z, t4.w};
                float hh[4] = {h4.x, h4.y, h4.z, h4.w};
                float r[4];
#pragma unroll
                for (int k = 0; k < 4; k++) {
                    int c = kk * 4 + k;
                    float mu = bnsum[c] * invN;
                    float var = bnsq[c] * invN - mu * mu;
                    float y = gamma[c] * (tt[k] - mu) * rsqrtf(var + 1e-5f) + beta[c];
                    float gl = 0.5f * y * (1.0f + erff(y * 0.70710678118654752f));
                    r[k] = gl + hh[k];
                }
                h4.x = r[0]; h4.y = r[1]; h4.z = r[2]; h4.w = r[3];
                reinterpret_cast<float4*>(g_h)[gn * 16 + kk] = h4;
            }
            float* p = &xs[nl * XS_STRIDE + kk * 4];
            p[0] = h4.x; p[1] = h4.y; p[2] = h4.z; p[3] = h4.w;
        }
    }
    for (int i = tid; i < 1024; i += 256) sWe[i] = We[i];
    if (tid < 64) sbe[tid] = be[tid];

    const float* Wm[4] = {Wq, Wk, Wv, Ws};
    const float* bm[4] = {bq, bk, bv, bs};

    const int warp = tid >> 5, lane = tid & 31;
    const int g4 = warp >> 1;
    const int chalf = warp & 1;
    const int grp = lane >> 2;
    const int qd = lane & 3;
    const int nl = tid & 63;
    const int quart = tid >> 6;
    const int gn = base + nl;

    for (int m = 0; m < 4; m++) {
        __syncthreads();
        {
            const float* wsrc = Wm[m];
            for (int i = tid; i < 4096; i += 256) {
                sW[(i >> 6) * SW_STRIDE + (i & 63)] = __uint_as_float(f2tf32(wsrc[i]));
            }
            if (tid < 64) sb[tid] = bm[m][tid];
        }
        __syncthreads();

        float acc[4][4];
#pragma unroll
        for (int t = 0; t < 4; t++)
#pragma unroll
            for (int d = 0; d < 4; d++) acc[t][d] = 0.0f;

#pragma unroll
        for (int ks = 0; ks < 8; ks++) {
            unsigned a[4];
            const float* xr = &xs[(g4 * 16 + grp) * XS_STRIDE + ks * 8 + qd];
            a[0] = f2tf32(xr[0]);
            a[2] = f2tf32(xr[4]);
            a[1] = f2tf32(xr[8 * XS_STRIDE]);
            a[3] = f2tf32(xr[8 * XS_STRIDE + 4]);
#pragma unroll
            for (int t = 0; t < 4; t++) {
                int cb = chalf * 32 + t * 8;
                unsigned b0 = __float_as_uint(sW[(ks * 8 + qd) * SW_STRIDE + cb + grp]);
                unsigned b1 = __float_as_uint(sW[(ks * 8 + qd + 4) * SW_STRIDE + cb + grp]);
                mma_tf32(acc[t], a, b0, b1);
            }
        }

        int r0 = g4 * 16 + grp;
        if (m == 3) {
#pragma unroll
            for (int t = 0; t < 4; t++) {
                int col = chalf * 32 + t * 8 + qd * 2;
                if (base + r0 < n) {
                    float2 o; o.x = acc[t][0] + sb[col]; o.y = acc[t][1] + sb[col + 1];
                    *reinterpret_cast<float2*>(g_skip + (size_t)(base + r0) * 64 + col) = o;
                }
                if (base + r0 + 8 < n) {
                    float2 o; o.x = acc[t][2] + sb[col]; o.y = acc[t][3] + sb[col + 1];
                    *reinterpret_cast<float2*>(g_skip + (size_t)(base + r0 + 8) * 64 + col) = o;
                }
            }
        } else {
#pragma unroll
            for (int t = 0; t < 4; t++) {
                int col = chalf * 32 + t * 8 + qd * 2;
                __half2 hlo = __floats2half2_rn(acc[t][0] + sb[col], acc[t][1] + sb[col + 1]);
                __half2 hhi = __floats2half2_rn(acc[t][2] + sb[col], acc[t][3] + sb[col + 1]);
                if (m == 0) {
                    *reinterpret_cast<__half2*>(&qbuf[r0 * 64 + col]) = hlo;
                    *reinterpret_cast<__half2*>(&qbuf[(r0 + 8) * 64 + col]) = hhi;
                } else {
                    __half2* dst = (m == 1) ? g_kh : g_vh;
                    if (base + r0 < n)     dst[(size_t)(base + r0) * 32 + (col >> 1)] = hlo;
                    if (base + r0 + 8 < n) dst[(size_t)(base + r0 + 8) * 32 + (col >> 1)] = hhi;
                }
            }
            if (m == 0) {
                __syncthreads();
                if (gn < n) {
                    uint4 u0 = *reinterpret_cast<const uint4*>(&qbuf[nl * 64 + quart * 16]);
                    uint4 u1 = *reinterpret_cast<const uint4*>(&qbuf[nl * 64 + quart * 16 + 8]);
                    uint4* qp = reinterpret_cast<uint4*>(g_qh + (size_t)gn * 32 + quart * 8);
                    qp[0] = u0; qp[1] = u1;
                    float qv[16];
                    unpack16(u0, u1, qv);
                    float pc[16];
#pragma unroll
                    for (int c = 0; c < 16; c++) {
                        const float4* wr = reinterpret_cast<const float4*>(&sWe[c * 64 + quart * 16]);
                        float s = 0.0f;
#pragma unroll
                        for (int j = 0; j < 4; j++) {
                            float4 w = wr[j];
                            s += w.x * qv[4 * j] + w.y * qv[4 * j + 1]
                               + w.z * qv[4 * j + 2] + w.w * qv[4 * j + 3];
                        }
                        pc[c] = s;
                    }
                    float rr = 0.0f;
#pragma unroll
                    for (int d = 0; d < 16; d++) rr += sbe[quart * 16 + d] * qv[d];
                    __half2 hp[8];
#pragma unroll
                    for (int j = 0; j < 8; j++) hp[j] = __floats2half2_rn(pc[2 * j], pc[2 * j + 1]);
                    uint4* pp = reinterpret_cast<uint4*>(g_ph + (size_t)gn * 32 + quart * 8);
                    pp[0] = *reinterpret_cast<uint4*>(&hp[0]);
                    pp[1] = *reinterpret_cast<uint4*>(&hp[4]);
                    g_r[gn * 4 + quart] = rr;
                }
            }
        }
    }
}

// ---------------- edge aggregation + finalize; lane = (node, head); zero shuffles, zero atomics ----------------
__global__ void edge_agg_kernel(const float* __restrict__ We, const float* __restrict__ be, int n) {
    __shared__ float sWe[16 * 64];
    __shared__ float sbe[64];
    const int tid = threadIdx.x;
    for (int i = tid; i < 1024; i += 256) sWe[i] = We[i];
    if (tid < 64) sbe[tid] = be[tid];
    __syncthreads();

    int idx = blockIdx.x * 256 + tid;   // (node, head)
    if (idx >= n * 4) return;
    const int node = idx >> 2;
    const int j = idx & 3;              // head; lane owns all 16 dims of head j

    // dst-side operands for head j (16 fp16 = 2 uint4), preconverted
    const uint4* qb = reinterpret_cast<const uint4*>(g_qh + (size_t)node * 32 + j * 8);
    const uint4* pb = reinterpret_cast<const uint4*>(g_ph + (size_t)node * 32 + j * 8);
    float qf[16], pf[16];
    unpack16(qb[0], qb[1], qf);
    unpack16(pb[0], pb[1], pf);
    const float rj = g_r[node * 4 + j];

    const int rs = g_row[node], re = g_row[node + 1];
    float at[16], as_[16], ad = 0.0f;
#pragma unroll
    for (int d = 0; d < 16; d++) { at[d] = 0.0f; as_[d] = 0.0f; }

    for (int pos = rs; pos < re; pos++) {
        int src = g_ssrc[pos];
        const uint4* eb = reinterpret_cast<const uint4*>(g_seah + (size_t)pos * 8);
        const uint4* kb = reinterpret_cast<const uint4*>(g_kh + (size_t)src * 32 + j * 8);
        const uint4* vb = reinterpret_cast<const uint4*>(g_vh + (size_t)src * 32 + j * 8);
        uint4 e0 = eb[0], e1 = eb[1];          // broadcast across quad
        uint4 k0 = kb[0], k1 = kb[1];          // quad covers full 128B row
        uint4 v0 = vb[0], v1 = vb[1];

        float ef[16], kf[16], vf[16];
        unpack16(e0, e1, ef);
        unpack16(k0, k1, kf);
        unpack16(v0, v1, vf);

        float a = rj;
#pragma unroll
        for (int d = 0; d < 16; d++) a += qf[d] * kf[d] + pf[d] * ef[d];
        float ex = __expf(a * 0.25f);
        ad += ex;
#pragma unroll
        for (int d = 0; d < 16; d++) {
            at[d] += ex * vf[d];
            as_[d] += ex * ef[d];
        }
    }

    // fused finalize (all lane-local): w[d] = sum_c We[c][j*16+d] * as_[c]
    float den = ad;
    float inv = 1.0f / (den + 1e-16f);
    const size_t obase = (size_t)node * 64 + j * 16;
#pragma unroll
    for (int dq = 0; dq < 4; dq++) {
        float w0 = 0.f, w1 = 0.f, w2 = 0.f, w3 = 0.f;
#pragma unroll
        for (int c = 0; c < 16; c++) {
            float sc = as_[c];
            float4 ww = *reinterpret_cast<const float4*>(&sWe[c * 64 + j * 16 + dq * 4]);
            w0 += sc * ww.x; w1 += sc * ww.y; w2 += sc * ww.z; w3 += sc * ww.w;
        }
        int ch = j * 16 + dq * 4;
        float4 sk = *reinterpret_cast<const float4*>(g_skip + obase + dq * 4);
        float4 o;
        o.x = (at[dq * 4 + 0] + w0 + den * sbe[ch + 0]) * inv + sk.x;
        o.y = (at[dq * 4 + 1] + w1 + den * sbe[ch + 1]) * inv + sk.y;
        o.z = (at[dq * 4 + 2] + w2 + den * sbe[ch + 2]) * inv + sk.z;
        o.w = (at[dq * 4 + 3] + w3 + den * sbe[ch + 3]) * inv + sk.w;
        *reinterpret_cast<float4*>(g_t + obase + dq * 4) = o;
    }
}

// ---------------- BN stats (into layer-indexed buffers) ----------------
__global__ void bn_stats_kernel(int n, int layer) {
    int tid = threadIdx.x;
    int c = tid & 63;
    int rowg = tid >> 6;
    float s = 0.0f, q = 0.0f;
    for (int r = blockIdx.x * 4 + rowg; r < n; r += gridDim.x * 4) {
        float v = g_t[(size_t)r * 64 + c];
        s += v; q += v * v;
    }
    __shared__ float ss[256], sq[256];
    ss[tid] = s; sq[tid] = q;
    __syncthreads();
    if (tid < 128) { ss[tid] += ss[tid + 128]; sq[tid] += sq[tid + 128]; }
    __syncthreads();
    if (tid < 64) {
        atomicAdd(&g_bnsum3[layer * 64 + tid], ss[tid] + ss[tid + 64]);
        atomicAdd(&g_bnsq3[layer * 64 + tid], sq[tid] + sq[tid + 64]);
    }
}

// ---------------- final BN apply + GELU + residual + fused pooling (layer 3 only) ----------------
__global__ void bn_apply_pool_kernel(const float* __restrict__ gamma, const float* __restrict__ beta,
                                     const int* __restrict__ batch, int layer, int n) {
    int idx = blockIdx.x * blockDim.x + threadIdx.x;
    if (idx >= n * 16) return;
    int node = idx >> 4;
    int c0 = (idx & 15) * 4;
    float invN = 1.0f / (float)n;
    float4 tv = reinterpret_cast<const float4*>(g_t)[idx];
    float4 hv = reinterpret_cast<const float4*>(g_h)[idx];
    float tt[4] = {tv.x, tv.y, tv.z, tv.w};
    float hh[4] = {hv.x, hv.y, hv.z, hv.w};
    float r[4];
#pragma unroll
    for (int k = 0; k < 4; k++) {
        int c = c0 + k;
        float mu = g_bnsum3[layer * 64 + c] * invN;
        float var = g_bnsq3[layer * 64 + c] * invN - mu * mu;
        float y = gamma[c] * (tt[k] - mu) * rsqrtf(var + 1e-5f) + beta[c];
        float gl = 0.5f * y * (1.0f + erff(y * 0.70710678118654752f));
        r[k] = gl + hh[k];
    }
    int g = batch[node];
    redAddV4(&g_pool[g * 64 + c0], r[0], r[1], r[2], r[3]);
    if (c0 == 0) atomicAdd(&g_cnt[g], 1.0f);
}

// ---------------- regressor ----------------
__global__ void reg_kernel(const float* __restrict__ rw1, const float* __restrict__ rb1,
                           const float* __restrict__ rw2, const float* __restrict__ rb2,
                           float* __restrict__ out) {
    int g = blockIdx.x;
    int tid = threadIdx.x;  // 128 threads
    __shared__ float feat[128];
    __shared__ float hred[64];
    float invc = 1.0f / fmaxf(g_cnt[g], 1.0f);
    float s = g_pool[g * 64 + (tid & 63)];
    feat[tid] = (tid < 64) ? s * invc : s;
    __syncthreads();
    if (tid < 64) {
        float acc = rb1[tid];
#pragma unroll 8
        for (int i = 0; i < 128; i++) acc += feat[i] * rw1[i * 64 + tid];
        acc = fmaxf(acc, 0.0f);
        hred[tid] = acc * rw2[tid];
    }
    __syncthreads();
    if (tid < 32) {
        float v = hred[tid] + hred[tid + 32];
#pragma unroll
        for (int off = 16; off > 0; off >>= 1) v += __shfl_down_sync(0xffffffffu, v, off);
        if (tid == 0) out[g] = v + rb2[0];
    }
}

// ---------------- host orchestration ----------------
extern "C" void kernel_launch(void* const* d_in, const int* in_sizes, int n_in,
                              void* d_out, int out_size) {
    const float* x      = (const float*)d_in[0];
    const int*   ei     = (const int*)d_in[1];
    const float* eattr  = (const float*)d_in[2];
    const int*   batch  = (const int*)d_in[3];
    const float* node_w = (const float*)d_in[4];
    const float* node_b = (const float*)d_in[5];
    const float* Wq = (const float*)d_in[6];
    const float* bq = (const float*)d_in[7];
    const float* Wk = (const float*)d_in[8];
    const float* bk = (const float*)d_in[9];
    const float* Wv = (const float*)d_in[10];
    const float* bv = (const float*)d_in[11];
    const float* We = (const float*)d_in[12];
    const float* be = (const float*)d_in[13];
    const float* Ws = (const float*)d_in[14];
    const float* bs = (const float*)d_in[15];
    const float* gamma = (const float*)d_in[16];
    const float* beta  = (const float*)d_in[17];
    const float* rw1 = (const float*)d_in[18];
    const float* rb1 = (const float*)d_in[19];
    const float* rw2 = (const float*)d_in[20];
    const float* rb2 = (const float*)d_in[21];
    float* out = (float*)d_out;

    int n = in_sizes[0] / 32;   // nodes
    int e = in_sizes[2] / 16;   // edges
    int G = out_size;           // graphs
    int nb = divup(n, 1024);

    float* ph;
    cudaGetSymbolAddress((void**)&ph, g_h);

    lin32_kernel<<<divup(n, 128), 128>>>(x, node_w, node_b, ph, n);

    // Build dst-sorted edge stream + CSR rows (once; reused by all 3 layers)
    hist_clear_kernel<<<divup(n, 256), 256>>>(n, G);
    hist_kernel<<<divup(e, 256), 256>>>(ei, e);
    scan1_kernel<<<nb, 1024>>>(n);
    scan2_kernel<<<1, 32>>>(nb);
    scan3_kernel<<<nb, 1024>>>(n);
    scatter_kernel<<<divup(e, 256), 256>>>(ei, eattr, e);

    float* psum; float* psq;
    cudaGetSymbolAddress((void**)&psum, g_bnsum3);
    cudaGetSymbolAddress((void**)&psq, g_bnsq3);

    for (int l = 0; l < 3; l++) {
        const float* wq = Wq + (size_t)l * 64 * 64;
        const float* wk = Wk + (size_t)l * 64 * 64;
        const float* wv = Wv + (size_t)l * 64 * 64;
        const float* ws = Ws + (size_t)l * 64 * 64;
        const float* we = We + (size_t)l * 16 * 64;

        qkvs_kernel<<<divup(n, 64), 256>>>(wq, bq + l * 64, wk, bk + l * 64,
                                           wv, bv + l * 64, ws, bs + l * 64,
                                           we, be + l * 64,
                                           gamma + (l - 1) * 64, beta + (l - 1) * 64,
                                           psum + (l - 1) * 64, psq + (l - 1) * 64,
                                           (l > 0) ? 1 : 0, n);
        edge_agg_kernel<<<divup((long long)n * 4, 256), 256>>>(we, be + l * 64, n);
        bn_stats_kernel<<<2048, 256>>>(n, l);
    }
    bn_apply_pool_kernel<<<divup((long long)n * 16, 256), 256>>>(gamma + 2 * 64, beta + 2 * 64,
                                                                 batch, 2, n);
    reg_kernel<<<G, 128>>>(rw1, rb1, rw2, rb2, out);
}